// round 1
// baseline (speedup 1.0000x reference)
#include <cuda_runtime.h>

#define NROWS 16384
#define K 128
#define D 64
#define ROWS_PER_BLOCK 8
#define NBLOCKS (NROWS / ROWS_PER_BLOCK)

// loss = mean over [N,K] of exp(-(soft_rank-1)/8) * dist
// soft_rank_k - 1 = sum_{j != k} sigmoid((d_k - d_j)/0.2)
//                 = (sum_all_j a_k/(a_k+a_j)) - 0.5,  a = exp(d/0.2)

__global__ __launch_bounds__(128) void dng_kernel(const float* __restrict__ data,
                                                  const float* __restrict__ weights,
                                                  float* __restrict__ out)
{
    __shared__ float4 x_s4[D / 4];            // current data row
    __shared__ float4 sa4[K / 4];             // a_j values
    __shared__ float warp_sums[4];

    const int k = threadIdx.x;                // centroid index, 0..127
    float* x_s = (float*)x_s4;
    float* sa  = (float*)sa4;

    // weights row k -> registers (64 floats)
    float4 w[16];
    const float4* wp = (const float4*)(weights + k * D);
#pragma unroll
    for (int i = 0; i < 16; i++) w[i] = wp[i];

    float acc = 0.0f;
    const int row0 = blockIdx.x * ROWS_PER_BLOCK;

    for (int r = 0; r < ROWS_PER_BLOCK; r++) {
        // stage data row into smem (write races none: prior reads fenced below)
        if (k < D) x_s[k] = data[(row0 + r) * D + k];
        __syncthreads();   // x ready; also fences prior-iter sa reads vs sa write

        // squared distance, direct form
        float d2 = 0.0f;
#pragma unroll
        for (int i = 0; i < 16; i++) {
            float4 xv = x_s4[i];              // broadcast LDS.128
            float t0 = xv.x - w[i].x;
            float t1 = xv.y - w[i].y;
            float t2 = xv.z - w[i].z;
            float t3 = xv.w - w[i].w;
            d2 = fmaf(t0, t0, d2);
            d2 = fmaf(t1, t1, d2);
            d2 = fmaf(t2, t2, d2);
            d2 = fmaf(t3, t3, d2);
        }
        float dist = sqrtf(fmaxf(d2, 0.0f));
        float a = __expf(dist * 5.0f);        // 1/TAU = 5
        sa[k] = a;
        __syncthreads();                      // sa ready

        // soft rank: sum_j a/(a + a_j); includes j==k term == 0.5
        float s = 0.0f;
#pragma unroll 8
        for (int jj = 0; jj < K / 4; jj++) {
            float4 v = sa4[jj];               // broadcast LDS.128
            s += __fdividef(a, a + v.x);
            s += __fdividef(a, a + v.y);
            s += __fdividef(a, a + v.z);
            s += __fdividef(a, a + v.w);
        }
        float rank_m1 = s - 0.5f;
        acc = fmaf(__expf(-rank_m1 * 0.125f), dist, acc);   // 1/LAMBDA = 0.125
        __syncthreads();                      // sum-loop sa reads done before next write
    }

    // block reduction -> global atomic
#pragma unroll
    for (int off = 16; off; off >>= 1)
        acc += __shfl_down_sync(0xFFFFFFFFu, acc, off);
    int wid = k >> 5;
    if ((k & 31) == 0) warp_sums[wid] = acc;
    __syncthreads();
    if (k == 0) {
        float t = warp_sums[0] + warp_sums[1] + warp_sums[2] + warp_sums[3];
        atomicAdd(out, t * (1.0f / ((float)NROWS * (float)K)));
    }
}

extern "C" void kernel_launch(void* const* d_in, const int* in_sizes, int n_in,
                              void* d_out, int out_size)
{
    const float* data    = (const float*)d_in[0];
    const float* weights = (const float*)d_in[1];
    float* out = (float*)d_out;

    cudaMemsetAsync(out, 0, sizeof(float));
    dng_kernel<<<NBLOCKS, 128>>>(data, weights, out);
}

// round 2
// speedup vs baseline: 1.1755x; 1.1755x over previous
#include <cuda_runtime.h>

#define NROWS 16384
#define K 128
#define D 64
#define RPB 8
#define NBLOCKS (NROWS / RPB)
#define LOG2E 1.4426950408889634f

// loss = mean_{n,k} exp(-(rank_k-1)/8) * d_k
// rank_k - 1 = sum_{j!=k} sigmoid((d_k-d_j)/0.2) = (sum_all_j a/(a+a_j)) - 0.5
// a = exp(5d - 20)  (rescaled; ratios invariant)
// batched: sum_{i=1..4} a/t_i = a * N * rcp(t1*t2*t3*t4),  N = p12*s34 + p34*s12

__global__ __launch_bounds__(128) void dng_kernel(const float* __restrict__ data,
                                                  const float* __restrict__ weights,
                                                  float* __restrict__ out)
{
    __shared__ float4 x_s4[D / 4];
    __shared__ float4 sa4[K / 4];
    __shared__ float x2_s[2];
    __shared__ float warp_sums[4];

    const int k = threadIdx.x;          // centroid 0..127
    const int lane = k & 31;
    const int wid = k >> 5;
    float* x_s = (float*)x_s4;

    // w' = -2*w in registers, c = |w|^2
    float4 w[16];
    float c = 0.0f;
    {
        const float4* wp = (const float4*)(weights + k * D);
#pragma unroll
        for (int i = 0; i < 16; i++) {
            float4 v = wp[i];
            c = fmaf(v.x, v.x, c); c = fmaf(v.y, v.y, c);
            c = fmaf(v.z, v.z, c); c = fmaf(v.w, v.w, c);
            v.x *= -2.0f; v.y *= -2.0f; v.z *= -2.0f; v.w *= -2.0f;
            w[i] = v;
        }
    }

    float acc = 0.0f;
    const int row0 = blockIdx.x * RPB;

    for (int r = 0; r < RPB; r++) {
        // stage row + compute |x|^2 once (warps 0,1 reduce)
        if (k < D) {
            float v = data[(row0 + r) * D + k];
            x_s[k] = v;
            float p = v * v;
#pragma unroll
            for (int o = 16; o; o >>= 1) p += __shfl_down_sync(0xFFFFFFFFu, p, o);
            if (lane == 0) x2_s[wid] = p;
        }
        __syncthreads();   // x ready; also fences prior-iter sa reads

        // d^2 = |x|^2 + |w|^2 - 2 x.w   (4 accumulators for ILP)
        float d0 = c, d1 = 0.0f, d2a = 0.0f, d3 = 0.0f;
#pragma unroll
        for (int i = 0; i < 16; i++) {
            float4 xv = x_s4[i];        // broadcast LDS.128
            d0  = fmaf(xv.x, w[i].x, d0);
            d1  = fmaf(xv.y, w[i].y, d1);
            d2a = fmaf(xv.z, w[i].z, d2a);
            d3  = fmaf(xv.w, w[i].w, d3);
        }
        float d2 = (d0 + d1) + (d2a + d3) + (x2_s[0] + x2_s[1]);
        float dist = sqrtf(fmaxf(d2, 0.0f));
        float a = exp2f(fmaf(dist, 5.0f * LOG2E, -20.0f * LOG2E));
        ((float*)sa4)[k] = a;
        __syncthreads();   // sa ready

        // soft-rank sum: one MUFU.RCP per 4 pairs
        float s = 0.0f;
#pragma unroll 8
        for (int jj = 0; jj < K / 4; jj++) {
            float4 b = sa4[jj];         // broadcast LDS.128
            float t1 = a + b.x, t2 = a + b.y, t3 = a + b.z, t4 = a + b.w;
            float p12 = t1 * t2, p34 = t3 * t4;
            float s12 = t1 + t2, s34 = t3 + t4;
            float N = fmaf(p34, s12, p12 * s34);
            float p = p12 * p34;
            float rp;
            asm("rcp.approx.f32 %0, %1;" : "=f"(rp) : "f"(p));
            s = fmaf(a * N, rp, s);
        }
        float rank_m1 = s - 0.5f;       // remove diagonal's 0.5
        float neigh = exp2f(-rank_m1 * (0.125f * LOG2E));
        acc = fmaf(neigh, dist, acc);
        __syncthreads();   // all sa reads done before next row overwrites
    }

    // block reduction -> global atomic
#pragma unroll
    for (int o = 16; o; o >>= 1) acc += __shfl_down_sync(0xFFFFFFFFu, acc, o);
    if (lane == 0) warp_sums[wid] = acc;
    __syncthreads();
    if (k == 0) {
        float t = warp_sums[0] + warp_sums[1] + warp_sums[2] + warp_sums[3];
        atomicAdd(out, t * (1.0f / ((float)NROWS * (float)K)));
    }
}

extern "C" void kernel_launch(void* const* d_in, const int* in_sizes, int n_in,
                              void* d_out, int out_size)
{
    const float* data    = (const float*)d_in[0];
    const float* weights = (const float*)d_in[1];
    float* out = (float*)d_out;

    cudaMemsetAsync(out, 0, sizeof(float));
    dng_kernel<<<NBLOCKS, 128>>>(data, weights, out);
}

// round 4
// speedup vs baseline: 1.3061x; 1.1112x over previous
#include <cuda_runtime.h>

#define NROWS 16384
#define K 128
#define D 64
#define RPB 8
#define NBLOCKS (NROWS / RPB)
#define LOG2E 1.4426950408889634f

typedef unsigned long long u64;

// f32x2 packed helpers (Blackwell; PTX-only, ptxas won't auto-fuse)
__device__ __forceinline__ u64 f2add(u64 a, u64 b) {
    u64 r; asm("add.rn.f32x2 %0, %1, %2;" : "=l"(r) : "l"(a), "l"(b)); return r;
}
__device__ __forceinline__ u64 f2mul(u64 a, u64 b) {
    u64 r; asm("mul.rn.f32x2 %0, %1, %2;" : "=l"(r) : "l"(a), "l"(b)); return r;
}
__device__ __forceinline__ u64 f2fma(u64 a, u64 b, u64 c) {
    u64 r; asm("fma.rn.f32x2 %0, %1, %2, %3;" : "=l"(r) : "l"(a), "l"(b), "l"(c)); return r;
}
__device__ __forceinline__ u64 fpack(float lo, float hi) {
    u64 r; asm("mov.b64 %0, {%1, %2};" : "=l"(r) : "f"(lo), "f"(hi)); return r;
}
__device__ __forceinline__ void funpack(u64 v, float& lo, float& hi) {
    asm("mov.b64 {%0, %1}, %2;" : "=f"(lo), "=f"(hi) : "l"(v));
}
__device__ __forceinline__ float frcp(float x) {
    float r; asm("rcp.approx.f32 %0, %1;" : "=f"(r) : "f"(x)); return r;
}
__device__ __forceinline__ float fex2(float x) {
    float r; asm("ex2.approx.f32 %0, %1;" : "=f"(r) : "f"(x)); return r;
}
__device__ __forceinline__ float fsqrt_(float x) {
    float r; asm("sqrt.approx.f32 %0, %1;" : "=f"(r) : "f"(x)); return r;
}

// loss = mean_{n,k} exp(-(rank_k-1)/8) * d_k
// rank_k-1 = (sum_all_j a/(a+a_j)) - 0.5,  a = exp(5d-20) (rescaled; ratios invariant)
// batched: sum_{i=1..4} a/t_i = a * N * rcp(t1 t2 t3 t4);
// two groups (j..j+3 | j+64..j+67) run per f32x2 lane pair.

__global__ __launch_bounds__(128) void dng_kernel(const float* __restrict__ data,
                                                  const float* __restrict__ weights,
                                                  float* __restrict__ out)
{
    // declared as ulonglong2 for guaranteed 16B alignment + legal 128-bit loads
    __shared__ ulonglong2 x_v[D / 4];     // current data row (float alias)
    __shared__ ulonglong2 sa_v[K / 4];    // interleaved: pairs (a_j, a_{j+64})
    __shared__ float x2_s[2];
    __shared__ float warp_sums[4];

    float* x_s = (float*)x_v;
    float* saq = (float*)sa_v;

    const int k = threadIdx.x;
    const int lane = k & 31;
    const int wid = k >> 5;

    // weights row k: packed pairs of -2*w, plus c = |w|^2
    u64 wv[D / 2];
    float c = 0.0f;
    {
        const float4* wp = (const float4*)(weights + k * D);
#pragma unroll
        for (int i = 0; i < D / 4; i++) {
            float4 v = wp[i];
            c = fmaf(v.x, v.x, c); c = fmaf(v.y, v.y, c);
            c = fmaf(v.z, v.z, c); c = fmaf(v.w, v.w, c);
            wv[2 * i]     = fpack(-2.0f * v.x, -2.0f * v.y);
            wv[2 * i + 1] = fpack(-2.0f * v.z, -2.0f * v.w);
        }
    }

    float acc = 0.0f;
    const int row0 = blockIdx.x * RPB;

    for (int r = 0; r < RPB; r++) {
        // stage data row + |x|^2 (warps 0,1)
        if (k < D) {
            float v = data[(row0 + r) * D + k];
            x_s[k] = v;
            float p = v * v;
#pragma unroll
            for (int o = 16; o; o >>= 1) p += __shfl_down_sync(0xFFFFFFFFu, p, o);
            if (lane == 0) x2_s[wid] = p;
        }
        __syncthreads();  // x ready; fences prior-iter saq reads

        // d^2 = |x|^2 + |w|^2 - 2 x.w  (packed dot, 2 accumulators)
        u64 dv0 = 0ull, dv1 = 0ull;   // 0x0 == packed {0.0f, 0.0f}
#pragma unroll
        for (int i = 0; i < D / 4; i++) {
            ulonglong2 xv = x_v[i];   // LDS.128 broadcast, compiler-ordered vs barrier
            dv0 = f2fma(xv.x, wv[2 * i],     dv0);
            dv1 = f2fma(xv.y, wv[2 * i + 1], dv1);
        }
        float e0, e1, e2, e3;
        funpack(dv0, e0, e1); funpack(dv1, e2, e3);
        float d2 = ((e0 + e1) + (e2 + e3)) + (c + (x2_s[0] + x2_s[1]));
        float dist = fsqrt_(fmaxf(d2, 0.0f));
        float a = fex2(fmaf(dist, 5.0f * LOG2E, -20.0f * LOG2E));

        // interleaved store: (a_j, a_{j+64}) adjacent
        if (k < 64) saq[2 * k] = a;
        else        saq[2 * (k - 64) + 1] = a;
        __syncthreads();  // saq ready

        // rank sum: 8 pairs/iter; lane A = group(4jj..4jj+3), lane B = +64
        const u64 av = fpack(a, a);
        u64 qv = 0ull;
#pragma unroll
        for (int jj = 0; jj < 16; jj++) {
            ulonglong2 b12 = sa_v[2 * jj];       // (a_{4jj},a_{4jj+64}) , (a_{4jj+1},...)
            ulonglong2 b34 = sa_v[2 * jj + 1];
            u64 tv1 = f2add(av, b12.x), tv2 = f2add(av, b12.y);
            u64 tv3 = f2add(av, b34.x), tv4 = f2add(av, b34.y);
            u64 p12 = f2mul(tv1, tv2), p34 = f2mul(tv3, tv4);
            u64 s12 = f2add(tv1, tv2), s34 = f2add(tv3, tv4);
            u64 Nv  = f2fma(p34, s12, f2mul(p12, s34));
            u64 pv  = f2mul(p12, p34);
            float pA, pB; funpack(pv, pA, pB);
            qv = f2fma(Nv, fpack(frcp(pA), frcp(pB)), qv);
        }
        float qA, qB; funpack(qv, qA, qB);
        float rank_m1 = a * (qA + qB) - 0.5f;   // diagonal removed
        acc = fmaf(fex2(-rank_m1 * (0.125f * LOG2E)), dist, acc);
        __syncthreads();  // saq reads done before next row overwrites
    }

    // block reduction -> global atomic
#pragma unroll
    for (int o = 16; o; o >>= 1) acc += __shfl_down_sync(0xFFFFFFFFu, acc, o);
    if (lane == 0) warp_sums[wid] = acc;
    __syncthreads();
    if (k == 0) {
        float t = warp_sums[0] + warp_sums[1] + warp_sums[2] + warp_sums[3];
        atomicAdd(out, t * (1.0f / ((float)NROWS * (float)K)));
    }
}

extern "C" void kernel_launch(void* const* d_in, const int* in_sizes, int n_in,
                              void* d_out, int out_size)
{
    const float* data    = (const float*)d_in[0];
    const float* weights = (const float*)d_in[1];
    float* out = (float*)d_out;

    cudaMemsetAsync(out, 0, sizeof(float));
    dng_kernel<<<NBLOCKS, 128>>>(data, weights, out);
}